// round 13
// baseline (speedup 1.0000x reference)
#include <cuda_runtime.h>
#include <cuda_bf16.h>

// kspaceMap: out (32,129,128,128) f32.
//   ch 0..127: sep[b,w,h,w'] = (Re(t)cos(2pi w w'/128) - Im(t)sin(..))/128,
//              t = row DFT_128 of input[:,0].
//   ch 128:    copy of input[b,1,:,:].  mask unused.
// Symmetries: sep[128-w]==sep[w]; value(w,w'+64) = (-1)^w value(w,w').
//
// R13 = R12 (32 regs, 8 CTAs/SM) with the DFT split into 4 u-quarters of
// 16 MACs (260 items over all 256 threads, serial rotation chain halved).

#define IM  128
#define BZ  32
#define CH_OUT 129

typedef unsigned long long u64;
#define SGNMASK 0x8000000080000000ull

static __device__ __forceinline__ u64 f2x(float a, float b) {
    u64 r; asm("mov.b64 %0, {%1, %2};" : "=l"(r) : "f"(a), "f"(b)); return r;
}
static __device__ __forceinline__ u64 mul2(u64 a, u64 b) {
    u64 d; asm("mul.rn.f32x2 %0, %1, %2;" : "=l"(d) : "l"(a), "l"(b)); return d;
}
static __device__ __forceinline__ u64 fma2(u64 a, u64 b, u64 c) {
    u64 d; asm("fma.rn.f32x2 %0, %1, %2, %3;" : "=l"(d) : "l"(a), "l"(b), "l"(c)); return d;
}
static __device__ __forceinline__ float2 unpk(u64 v) {
    float2 r; asm("mov.b64 {%0, %1}, %2;" : "=f"(r.x), "=f"(r.y) : "l"(v)); return r;
}

__global__ void __launch_bounds__(256, 8) kspace_kernel(const float* __restrict__ in,
                                                        float* __restrict__ out)
{
    const int bh   = blockIdx.x;
    const int b    = bh >> 7;
    const int h    = bh & (IM - 1);
    const int tid  = threadIdx.x;
    const int wj   = tid >> 5;
    const int lane = tid & 31;

    __shared__ float2 TW[IM];            // (cos,sin)(2*pi*k/128)
    __shared__ float  yy[130];           // y+ [0..63], y- [65..128]
    __shared__ float  pre[260], pim[260];
    __shared__ float2 tws[65];

    if (tid < IM) {
        float s, c;  sincospif((float)tid * (1.0f / 64.0f), &s, &c);
        TW[tid] = make_float2(c, s);
    }

    // ch128 row copy (warp 5) — independent of smem, overlaps everything
    if (wj == 5) {
        const unsigned o = (((unsigned)b * 2 + 1) << 14) + ((unsigned)h << 7) + 4u * lane;
        const float4 cp = __ldcs((const float4*)(in + o));
        __stcs((float4*)(out + ((((unsigned)(b * CH_OUT + IM)) << 14) + ((unsigned)h << 7)) + 4u * lane), cp);
    }

    // merged load + u-fold (64 threads, 2 LDG each)
    if (tid < 64) {
        const unsigned base = (((unsigned)b * 2) << 14) + ((unsigned)h << 7) + tid;
        const float a = in[base];
        const float d = in[base + 64];
        yy[tid]      = a + d;
        yy[65 + tid] = a - d;
    }
    __syncthreads();

    // ---- DFT: 260 items = (bin w 0..64) x (u-quarter q 0..3), 16 MACs each ----
    for (int i = tid; i < 260; i += 256) {
        const int w = i % 65;
        const int q = i / 65;
        const float2 stp = TW[w];                           // step e(2pi w/128)
        const float2 st0 = TW[(16 * q * w) & (IM - 1)];     // start u0 = 16q (exact)
        const float SC = stp.x, SS = stp.y;
        float c = st0.x, s = st0.y;
        const float* yp = yy + (w & 1) * 65 + 16 * q;
        float re = 0.0f, im = 0.0f;
        #pragma unroll
        for (int u = 0; u < 16; ++u) {
            const float yv = yp[u];
            re = fmaf(yv,  c, re);
            im = fmaf(yv, -s, im);
            const float cn = fmaf(c, SC, -(s * SS));
            s = fmaf(s, SC, c * SS);
            c = cn;
        }
        pre[i] = re;  pim[i] = im;
    }
    __syncthreads();
    if (tid < 65) {
        tws[tid] = make_float2(
            ((pre[tid] + pre[tid + 65]) + (pre[tid + 130] + pre[tid + 195])) * (1.0f / IM),
            ((pim[tid] + pim[tid + 65]) + (pim[tid + 130] + pim[tid + 195])) * (1.0f / IM));
    }
    __syncthreads();

    // ---- Store stage (identical to R12) ----
    {
        const int half = lane >> 4;
        const int l16  = lane & 15;
        const int wstart = wj + 8 * half;       // 0..15

        u64 C01, S01, C23, S23, SC01, SS01;
        {
            float2 a0 = TW[(wstart * (4 * l16 + 0)) & 127];
            float2 a1 = TW[(wstart * (4 * l16 + 1)) & 127];
            float2 a2 = TW[(wstart * (4 * l16 + 2)) & 127];
            float2 a3 = TW[(wstart * (4 * l16 + 3)) & 127];
            C01 = f2x(a0.x, a1.x);  S01 = f2x(a0.y, a1.y);
            C23 = f2x(a2.x, a3.x);  S23 = f2x(a2.y, a3.y);
            float2 s0 = TW[(16 * (4 * l16 + 0)) & 127];
            float2 s1 = TW[(16 * (4 * l16 + 1)) & 127];
            SC01 = f2x(s0.x, s1.x);  SS01 = f2x(s0.y, s1.y);
            // chain-23 step = chain-01 step + pi/2: (cos,sin) = (-SS01, SC01)
        }
        const u64 sgn  = (wstart & 1) ? SGNMASK : 0ull;
        const bool m0skip = (wstart == 0);

        const unsigned offA = (((unsigned)(b * CH_OUT + wstart))        << 14)
                            + ((unsigned)h << 7) + 4u * l16;
        const unsigned offM = (((unsigned)(b * CH_OUT + (IM - wstart))) << 14)
                            + ((unsigned)h << 7) + 4u * l16;

        #pragma unroll
        for (int s = 0; s < 4; ++s) {
            const int w = wstart + 16 * s;                 // <= 63
            const float2 tt = tws[w];
            const u64 trx = f2x(tt.x, tt.x);
            const float nti = -tt.y;
            const u64 ntx = f2x(nti, nti);
            const u64 v01 = fma2(ntx, S01, mul2(trx, C01));
            const u64 v23 = fma2(ntx, S23, mul2(trx, C23));
            const u64 h01 = v01 ^ sgn, h23 = v23 ^ sgn;
            const float2 a = unpk(v01), d = unpk(v23);
            const float2 ah = unpk(h01), dh = unpk(h23);
            const float4 vlo = make_float4(a.x, a.y, d.x, d.y);
            const float4 vhi = make_float4(ah.x, ah.y, dh.x, dh.y);
            __stcs((float4*)(out + offA + (unsigned)s * 262144u), vlo);
            __stcs((float4*)(out + offA + (unsigned)s * 262144u + 64u), vhi);
            if (s || !m0skip) {
                __stcs((float4*)(out + offM - (unsigned)s * 262144u), vlo);
                __stcs((float4*)(out + offM - (unsigned)s * 262144u + 64u), vhi);
            }
            const u64 nC01 = fma2(S01, SS01 ^ SGNMASK, mul2(C01, SC01));
            S01 = fma2(C01, SS01, mul2(S01, SC01));
            C01 = nC01;
            const u64 nC23 = fma2(C23, SS01, mul2(S23, SC01)) ^ SGNMASK;
            S23 = fma2(S23, SS01 ^ SGNMASK, mul2(C23, SC01));
            C23 = nC23;
        }

        // w = 64 tail (warp 0, half 0): mirror(64)==64, store once.
        if (wj == 0 && half == 0) {
            const float2 tt = tws[64];
            const u64 trx = f2x(tt.x, tt.x);
            const float nti = -tt.y;
            const u64 ntx = f2x(nti, nti);
            const u64 v01 = fma2(ntx, S01, mul2(trx, C01));
            const u64 v23 = fma2(ntx, S23, mul2(trx, C23));
            const u64 h01 = v01 ^ sgn, h23 = v23 ^ sgn;
            const float2 a = unpk(v01), d = unpk(v23);
            const float2 ah = unpk(h01), dh = unpk(h23);
            __stcs((float4*)(out + offA + 4u * 262144u),       make_float4(a.x, a.y, d.x, d.y));
            __stcs((float4*)(out + offA + 4u * 262144u + 64u), make_float4(ah.x, ah.y, dh.x, dh.y));
        }
    }
}

extern "C" void kernel_launch(void* const* d_in, const int* in_sizes, int n_in,
                              void* d_out, int out_size)
{
    const float* in  = (const float*)d_in[0];   // (32,2,128,128) f32
    float*       out = (float*)d_out;           // (32,129,128,128) f32
    (void)in_sizes; (void)n_in; (void)out_size;

    kspace_kernel<<<BZ * IM, 256>>>(in, out);
}

// round 15
// speedup vs baseline: 1.0049x; 1.0049x over previous
#include <cuda_runtime.h>
#include <cuda_bf16.h>

// kspaceMap: out (32,129,128,128) f32.
//   ch 0..127: sep[b,w,h,w'] = (Re(t)cos(2pi w w'/128) - Im(t)sin(..))/128,
//              t = row DFT_128 of input[:,0].
//   ch 128:    copy of input[b,1,:,:].  mask unused.
// Symmetries: sep[128-w]==sep[w]; value(w,w'+64) = (-1)^w value(w,w').
//
// R15 = R14 with bin-64 fixed: w=64 is EVEN, so t64 = sum y+[u]*(-1)^u (y+ table,
// not y-). DFT: 256 items (w=tid&63, q=tid>>6, 16 MACs, chain halved vs R12).
// Store stage identical to R12 (32 regs, 8 CTAs/SM).

#define IM  128
#define BZ  32
#define CH_OUT 129

typedef unsigned long long u64;
#define SGNMASK 0x8000000080000000ull

static __device__ __forceinline__ u64 f2x(float a, float b) {
    u64 r; asm("mov.b64 %0, {%1, %2};" : "=l"(r) : "f"(a), "f"(b)); return r;
}
static __device__ __forceinline__ u64 mul2(u64 a, u64 b) {
    u64 d; asm("mul.rn.f32x2 %0, %1, %2;" : "=l"(d) : "l"(a), "l"(b)); return d;
}
static __device__ __forceinline__ u64 fma2(u64 a, u64 b, u64 c) {
    u64 d; asm("fma.rn.f32x2 %0, %1, %2, %3;" : "=l"(d) : "l"(a), "l"(b), "l"(c)); return d;
}
static __device__ __forceinline__ float2 unpk(u64 v) {
    float2 r; asm("mov.b64 {%0, %1}, %2;" : "=f"(r.x), "=f"(r.y) : "l"(v)); return r;
}

__global__ void __launch_bounds__(256, 8) kspace_kernel(const float* __restrict__ in,
                                                        float* __restrict__ out)
{
    const int bh   = blockIdx.x;
    const int b    = bh >> 7;
    const int h    = bh & (IM - 1);
    const int tid  = threadIdx.x;
    const int wj   = tid >> 5;
    const int lane = tid & 31;

    __shared__ float2 TW[IM];            // (cos,sin)(2*pi*k/128)
    __shared__ float  yy[130];           // y+ [0..63], y- [65..128]
    __shared__ float  pre[256], pim[256];
    __shared__ float2 tws[65];

    if (tid < IM) {
        float s, c;  sincospif((float)tid * (1.0f / 64.0f), &s, &c);
        TW[tid] = make_float2(c, s);
    }

    // ch128 row copy (warp 5) — overlaps with table/fold
    if (wj == 5) {
        const unsigned o = (((unsigned)b * 2 + 1) << 14) + ((unsigned)h << 7) + 4u * lane;
        const float4 cp = __ldcs((const float4*)(in + o));
        __stcs((float4*)(out + ((((unsigned)(b * CH_OUT + IM)) << 14) + ((unsigned)h << 7)) + 4u * lane), cp);
    }

    // merged load + u-fold (64 threads, 2 LDG each)
    if (tid < 64) {
        const unsigned base = (((unsigned)b * 2) << 14) + ((unsigned)h << 7) + tid;
        const float a = in[base];
        const float d = in[base + 64];
        yy[tid]      = a + d;
        yy[65 + tid] = a - d;
    }
    __syncthreads();

    // ---- DFT: 256 items = (bin w = tid&63) x (u-quarter q = tid>>6), 16 MACs ----
    {
        const int w = tid & 63;
        const int q = tid >> 6;
        const float2 stp = TW[w];                            // step e(2pi w/128)
        const float2 st0 = TW[(16 * q * w) & (IM - 1)];      // start u0 = 16q (exact)
        const float SC = stp.x, SS = stp.y;
        float c = st0.x, s = st0.y;
        const float* yp = yy + (w & 1) * 65 + 16 * q;
        float re = 0.0f, im = 0.0f;
        #pragma unroll
        for (int u = 0; u < 16; ++u) {
            const float yv = yp[u];
            re = fmaf(yv,  c, re);
            im = fmaf(yv, -s, im);
            const float cn = fmaf(c, SC, -(s * SS));
            s = fmaf(s, SC, c * SS);
            c = cn;
        }
        pre[tid] = re;  pim[tid] = im;
    }
    __syncthreads();
    // combine bins 0..63 (tid<64); bin 64 by warp 2 shuffle reduction on y+ (even bin!)
    if (tid < 64) {
        tws[tid] = make_float2(
            ((pre[tid] + pre[tid + 64]) + (pre[tid + 128] + pre[tid + 192])) * (1.0f / IM),
            ((pim[tid] + pim[tid + 64]) + (pim[tid + 128] + pim[tid + 192])) * (1.0f / IM));
    } else if (tid < 96) {               // warp 2: t64 = sum_{u<64} y+[u]*(-1)^u
        const int l = tid - 64;
        float v = yy[l] + yy[l + 32];    // (-1)^l == (-1)^(l+32)
        if (l & 1) v = -v;
        #pragma unroll
        for (int o = 16; o > 0; o >>= 1)
            v += __shfl_xor_sync(0xffffffffu, v, o);
        if (l == 0) tws[64] = make_float2(v * (1.0f / IM), 0.0f);
    }
    __syncthreads();

    // ---- Store stage (identical to R12) ----
    {
        const int half = lane >> 4;
        const int l16  = lane & 15;
        const int wstart = wj + 8 * half;       // 0..15

        u64 C01, S01, C23, S23, SC01, SS01;
        {
            float2 a0 = TW[(wstart * (4 * l16 + 0)) & 127];
            float2 a1 = TW[(wstart * (4 * l16 + 1)) & 127];
            float2 a2 = TW[(wstart * (4 * l16 + 2)) & 127];
            float2 a3 = TW[(wstart * (4 * l16 + 3)) & 127];
            C01 = f2x(a0.x, a1.x);  S01 = f2x(a0.y, a1.y);
            C23 = f2x(a2.x, a3.x);  S23 = f2x(a2.y, a3.y);
            float2 s0 = TW[(16 * (4 * l16 + 0)) & 127];
            float2 s1 = TW[(16 * (4 * l16 + 1)) & 127];
            SC01 = f2x(s0.x, s1.x);  SS01 = f2x(s0.y, s1.y);
            // chain-23 step = chain-01 step + pi/2: (cos,sin) = (-SS01, SC01)
        }
        const u64 sgn  = (wstart & 1) ? SGNMASK : 0ull;
        const bool m0skip = (wstart == 0);

        const unsigned offA = (((unsigned)(b * CH_OUT + wstart))        << 14)
                            + ((unsigned)h << 7) + 4u * l16;
        const unsigned offM = (((unsigned)(b * CH_OUT + (IM - wstart))) << 14)
                            + ((unsigned)h << 7) + 4u * l16;

        #pragma unroll
        for (int s = 0; s < 4; ++s) {
            const int w = wstart + 16 * s;                 // <= 63
            const float2 tt = tws[w];
            const u64 trx = f2x(tt.x, tt.x);
            const float nti = -tt.y;
            const u64 ntx = f2x(nti, nti);
            const u64 v01 = fma2(ntx, S01, mul2(trx, C01));
            const u64 v23 = fma2(ntx, S23, mul2(trx, C23));
            const u64 h01 = v01 ^ sgn, h23 = v23 ^ sgn;
            const float2 a = unpk(v01), d = unpk(v23);
            const float2 ah = unpk(h01), dh = unpk(h23);
            const float4 vlo = make_float4(a.x, a.y, d.x, d.y);
            const float4 vhi = make_float4(ah.x, ah.y, dh.x, dh.y);
            __stcs((float4*)(out + offA + (unsigned)s * 262144u), vlo);
            __stcs((float4*)(out + offA + (unsigned)s * 262144u + 64u), vhi);
            if (s || !m0skip) {
                __stcs((float4*)(out + offM - (unsigned)s * 262144u), vlo);
                __stcs((float4*)(out + offM - (unsigned)s * 262144u + 64u), vhi);
            }
            const u64 nC01 = fma2(S01, SS01 ^ SGNMASK, mul2(C01, SC01));
            S01 = fma2(C01, SS01, mul2(S01, SC01));
            C01 = nC01;
            const u64 nC23 = fma2(C23, SS01, mul2(S23, SC01)) ^ SGNMASK;
            S23 = fma2(S23, SS01 ^ SGNMASK, mul2(C23, SC01));
            C23 = nC23;
        }

        // w = 64 tail (warp 0, half 0): mirror(64)==64, store once.
        if (wj == 0 && half == 0) {
            const float2 tt = tws[64];
            const u64 trx = f2x(tt.x, tt.x);
            const float nti = -tt.y;
            const u64 ntx = f2x(nti, nti);
            const u64 v01 = fma2(ntx, S01, mul2(trx, C01));
            const u64 v23 = fma2(ntx, S23, mul2(trx, C23));
            const u64 h01 = v01 ^ sgn, h23 = v23 ^ sgn;
            const float2 a = unpk(v01), d = unpk(v23);
            const float2 ah = unpk(h01), dh = unpk(h23);
            __stcs((float4*)(out + offA + 4u * 262144u),       make_float4(a.x, a.y, d.x, d.y));
            __stcs((float4*)(out + offA + 4u * 262144u + 64u), make_float4(ah.x, ah.y, dh.x, dh.y));
        }
    }
}

extern "C" void kernel_launch(void* const* d_in, const int* in_sizes, int n_in,
                              void* d_out, int out_size)
{
    const float* in  = (const float*)d_in[0];   // (32,2,128,128) f32
    float*       out = (float*)d_out;           // (32,129,128,128) f32
    (void)in_sizes; (void)n_in; (void)out_size;

    kspace_kernel<<<BZ * IM, 256>>>(in, out);
}

// round 16
// speedup vs baseline: 1.0135x; 1.0085x over previous
#include <cuda_runtime.h>
#include <cuda_bf16.h>

// kspaceMap: out (32,129,128,128) f32.
//   ch 0..127: sep[b,w,h,w'] = (Re(t)cos(2pi w w'/128) - Im(t)sin(..))/128,
//              t = row DFT_128 of input[:,0].
//   ch 128:    copy of input[b,1,:,:].  mask unused.
// Symmetries: sep[128-w]==sep[w] (real input); value(w,w'+64) = (-1)^w value(w,w').
//
// R16 (final): R15 with the input LDGs hoisted ahead of the twiddle-table MUFU
// work so load latency overlaps table build. At the HBM write ceiling:
// DRAM ~65%, occ 85%, issue 29% — all structural families converge here.
//
// Pipeline per CTA (one (b,h) row, 256 thr, 32 regs, 8 CTAs/SM):
//  1. TW[128] twiddle table: 1 sincospif/thread (exact grid angles).
//  2. warp 5: ch128 passthrough copy (overlaps everything).
//  3. tid<64: LDG x[u], x[u+64] (issued first) -> u-fold y+/- in smem.
//  4. DFT: 256 items (bin w = tid&63, u-quarter q = tid>>6), 16 MACs each via
//     register rotation with exact TW starts; bin 64 = warp-2 shfl on y+.
//  5. Store: half-warp bin chains (w = wj+8*half, step 16), lane slot owns 4 w'
//     (STG.128) + quarter-wave partner (+64, sign flip) + mirror channel 128-w;
//     packed f32x2 rotations, .cs streaming hints.

#define IM  128
#define BZ  32
#define CH_OUT 129

typedef unsigned long long u64;
#define SGNMASK 0x8000000080000000ull

static __device__ __forceinline__ u64 f2x(float a, float b) {
    u64 r; asm("mov.b64 %0, {%1, %2};" : "=l"(r) : "f"(a), "f"(b)); return r;
}
static __device__ __forceinline__ u64 mul2(u64 a, u64 b) {
    u64 d; asm("mul.rn.f32x2 %0, %1, %2;" : "=l"(d) : "l"(a), "l"(b)); return d;
}
static __device__ __forceinline__ u64 fma2(u64 a, u64 b, u64 c) {
    u64 d; asm("fma.rn.f32x2 %0, %1, %2, %3;" : "=l"(d) : "l"(a), "l"(b), "l"(c)); return d;
}
static __device__ __forceinline__ float2 unpk(u64 v) {
    float2 r; asm("mov.b64 {%0, %1}, %2;" : "=f"(r.x), "=f"(r.y) : "l"(v)); return r;
}

__global__ void __launch_bounds__(256, 8) kspace_kernel(const float* __restrict__ in,
                                                        float* __restrict__ out)
{
    const int bh   = blockIdx.x;
    const int b    = bh >> 7;
    const int h    = bh & (IM - 1);
    const int tid  = threadIdx.x;
    const int wj   = tid >> 5;
    const int lane = tid & 31;

    __shared__ float2 TW[IM];            // (cos,sin)(2*pi*k/128)
    __shared__ float  yy[130];           // y+ [0..63], y- [65..128]
    __shared__ float  pre[256], pim[256];
    __shared__ float2 tws[65];

    // LDGs first: latency overlaps the MUFU table build below.
    float xa = 0.0f, xd = 0.0f;
    if (tid < 64) {
        const unsigned base = (((unsigned)b * 2) << 14) + ((unsigned)h << 7) + tid;
        xa = in[base];
        xd = in[base + 64];
    }
    float4 cp;
    if (wj == 5) {
        const unsigned o = (((unsigned)b * 2 + 1) << 14) + ((unsigned)h << 7) + 4u * lane;
        cp = __ldcs((const float4*)(in + o));
    }

    if (tid < IM) {
        float s, c;  sincospif((float)tid * (1.0f / 64.0f), &s, &c);
        TW[tid] = make_float2(c, s);
    }

    if (tid < 64) {
        yy[tid]      = xa + xd;
        yy[65 + tid] = xa - xd;
    }
    if (wj == 5) {
        __stcs((float4*)(out + ((((unsigned)(b * CH_OUT + IM)) << 14) + ((unsigned)h << 7)) + 4u * lane), cp);
    }
    __syncthreads();

    // ---- DFT: 256 items = (bin w = tid&63) x (u-quarter q = tid>>6), 16 MACs ----
    {
        const int w = tid & 63;
        const int q = tid >> 6;
        const float2 stp = TW[w];                            // step e(2pi w/128)
        const float2 st0 = TW[(16 * q * w) & (IM - 1)];      // start u0 = 16q (exact)
        const float SC = stp.x, SS = stp.y;
        float c = st0.x, s = st0.y;
        const float* yp = yy + (w & 1) * 65 + 16 * q;
        float re = 0.0f, im = 0.0f;
        #pragma unroll
        for (int u = 0; u < 16; ++u) {
            const float yv = yp[u];
            re = fmaf(yv,  c, re);
            im = fmaf(yv, -s, im);
            const float cn = fmaf(c, SC, -(s * SS));
            s = fmaf(s, SC, c * SS);
            c = cn;
        }
        pre[tid] = re;  pim[tid] = im;
    }
    __syncthreads();
    // combine bins 0..63 (tid<64); bin 64 (EVEN -> y+ table) by warp-2 shuffle
    if (tid < 64) {
        tws[tid] = make_float2(
            ((pre[tid] + pre[tid + 64]) + (pre[tid + 128] + pre[tid + 192])) * (1.0f / IM),
            ((pim[tid] + pim[tid + 64]) + (pim[tid + 128] + pim[tid + 192])) * (1.0f / IM));
    } else if (tid < 96) {               // t64 = sum_{u<64} y+[u]*(-1)^u
        const int l = tid - 64;
        float v = yy[l] + yy[l + 32];    // (-1)^l == (-1)^(l+32)
        if (l & 1) v = -v;
        #pragma unroll
        for (int o = 16; o > 0; o >>= 1)
            v += __shfl_xor_sync(0xffffffffu, v, o);
        if (l == 0) tws[64] = make_float2(v * (1.0f / IM), 0.0f);
    }
    __syncthreads();

    // ---- Store stage (R12-proven) ----
    {
        const int half = lane >> 4;
        const int l16  = lane & 15;
        const int wstart = wj + 8 * half;       // 0..15

        u64 C01, S01, C23, S23, SC01, SS01;
        {
            float2 a0 = TW[(wstart * (4 * l16 + 0)) & 127];
            float2 a1 = TW[(wstart * (4 * l16 + 1)) & 127];
            float2 a2 = TW[(wstart * (4 * l16 + 2)) & 127];
            float2 a3 = TW[(wstart * (4 * l16 + 3)) & 127];
            C01 = f2x(a0.x, a1.x);  S01 = f2x(a0.y, a1.y);
            C23 = f2x(a2.x, a3.x);  S23 = f2x(a2.y, a3.y);
            float2 s0 = TW[(16 * (4 * l16 + 0)) & 127];
            float2 s1 = TW[(16 * (4 * l16 + 1)) & 127];
            SC01 = f2x(s0.x, s1.x);  SS01 = f2x(s0.y, s1.y);
            // chain-23 step = chain-01 step + pi/2: (cos,sin) = (-SS01, SC01)
        }
        const u64 sgn  = (wstart & 1) ? SGNMASK : 0ull;
        const bool m0skip = (wstart == 0);

        const unsigned offA = (((unsigned)(b * CH_OUT + wstart))        << 14)
                            + ((unsigned)h << 7) + 4u * l16;
        const unsigned offM = (((unsigned)(b * CH_OUT + (IM - wstart))) << 14)
                            + ((unsigned)h << 7) + 4u * l16;

        #pragma unroll
        for (int s = 0; s < 4; ++s) {
            const int w = wstart + 16 * s;                 // <= 63
            const float2 tt = tws[w];
            const u64 trx = f2x(tt.x, tt.x);
            const float nti = -tt.y;
            const u64 ntx = f2x(nti, nti);
            const u64 v01 = fma2(ntx, S01, mul2(trx, C01));
            const u64 v23 = fma2(ntx, S23, mul2(trx, C23));
            const u64 h01 = v01 ^ sgn, h23 = v23 ^ sgn;
            const float2 a = unpk(v01), d = unpk(v23);
            const float2 ah = unpk(h01), dh = unpk(h23);
            const float4 vlo = make_float4(a.x, a.y, d.x, d.y);
            const float4 vhi = make_float4(ah.x, ah.y, dh.x, dh.y);
            __stcs((float4*)(out + offA + (unsigned)s * 262144u), vlo);
            __stcs((float4*)(out + offA + (unsigned)s * 262144u + 64u), vhi);
            if (s || !m0skip) {
                __stcs((float4*)(out + offM - (unsigned)s * 262144u), vlo);
                __stcs((float4*)(out + offM - (unsigned)s * 262144u + 64u), vhi);
            }
            const u64 nC01 = fma2(S01, SS01 ^ SGNMASK, mul2(C01, SC01));
            S01 = fma2(C01, SS01, mul2(S01, SC01));
            C01 = nC01;
            const u64 nC23 = fma2(C23, SS01, mul2(S23, SC01)) ^ SGNMASK;
            S23 = fma2(S23, SS01 ^ SGNMASK, mul2(C23, SC01));
            C23 = nC23;
        }

        // w = 64 tail (warp 0, half 0): mirror(64)==64, store once.
        if (wj == 0 && half == 0) {
            const float2 tt = tws[64];
            const u64 trx = f2x(tt.x, tt.x);
            const float nti = -tt.y;
            const u64 ntx = f2x(nti, nti);
            const u64 v01 = fma2(ntx, S01, mul2(trx, C01));
            const u64 v23 = fma2(ntx, S23, mul2(trx, C23));
            const u64 h01 = v01 ^ sgn, h23 = v23 ^ sgn;
            const float2 a = unpk(v01), d = unpk(v23);
            const float2 ah = unpk(h01), dh = unpk(h23);
            __stcs((float4*)(out + offA + 4u * 262144u),       make_float4(a.x, a.y, d.x, d.y));
            __stcs((float4*)(out + offA + 4u * 262144u + 64u), make_float4(ah.x, ah.y, dh.x, dh.y));
        }
    }
}

extern "C" void kernel_launch(void* const* d_in, const int* in_sizes, int n_in,
                              void* d_out, int out_size)
{
    const float* in  = (const float*)d_in[0];   // (32,2,128,128) f32
    float*       out = (float*)d_out;           // (32,129,128,128) f32
    (void)in_sizes; (void)n_in; (void)out_size;

    kspace_kernel<<<BZ * IM, 256>>>(in, out);
}